// round 15
// baseline (speedup 1.0000x reference)
#include <cuda_runtime.h>
#include <cuda_bf16.h>
#include <cstdint>

// ---------------- problem constants ----------------
#define KSNAP 8
#define NNODE 10000
#define NEDGE 160000
#define EPTOT (NEDGE + NNODE)   // edges + self loops = 170000
#define HEADS 8
#define D2 256
#define LH 256
#define NEG 0.2f
#define NTOT (KSNAP * NNODE)    // 80000
#define ETOT (KSNAP * EPTOT)    // 1360000
#define CAP 64                  // adjacency bucket capacity

// ---------------- static scratch ----------------
static __device__ unsigned int g_featb[NTOT * 128];    // h_lin bf16x2 packed
static __device__ float g_ssrc[NTOT * HEADS];
static __device__ float g_sdst[NTOT * HEADS];
static __device__ float g_q   [2 * HEADS];
static __device__ float g_theta[HEADS * 32];
static __device__ float g_tab  [HEADS * 33 * 2 * 256];
static __device__ int   g_pos [KSNAP * NNODE];
static __device__ int   g_adjB[NTOT * CAP];
static __device__ float g_emb [KSNAP * D2];
static __device__ float g_xw  [2 * KSNAP * 4 * LH];
static __device__ float2 g_whhT2[2 * 128 * 1024];

// ---------------- helpers ----------------
__device__ __forceinline__ float warp_sum(float v) {
#pragma unroll
    for (int o = 16; o; o >>= 1) v += __shfl_xor_sync(0xffffffffu, v, o);
    return v;
}
__device__ __forceinline__ float warp_max(float v) {
#pragma unroll
    for (int o = 16; o; o >>= 1) v = fmaxf(v, __shfl_xor_sync(0xffffffffu, v, o));
    return v;
}
__device__ __forceinline__ float warp_min(float v) {
#pragma unroll
    for (int o = 16; o; o >>= 1) v = fminf(v, __shfl_xor_sync(0xffffffffu, v, o));
    return v;
}
#define FMA2(d, a, b) asm("fma.rn.f32x2 %0, %1, %2, %0;" : "+l"(d) : "l"(a), "l"(b))
__device__ __forceinline__ unsigned long long dup2(float a) {
    unsigned long long r;
    asm("mov.b64 %0, {%1, %1};" : "=l"(r) : "r"(__float_as_uint(a)));
    return r;
}
__device__ __forceinline__ unsigned long long bf2f2(unsigned int w) {
    unsigned int lo = w << 16;
    unsigned int hi = w & 0xffff0000u;
    unsigned long long r;
    asm("mov.b64 %0, {%1, %2};" : "=l"(r) : "r"(lo), "r"(hi));
    return r;
}
__device__ __forceinline__ void unpack2(unsigned long long v, float& lo, float& hi) {
    lo = __uint_as_float((unsigned int)(v & 0xffffffffull));
    hi = __uint_as_float((unsigned int)(v >> 32));
}
__device__ __forceinline__ float lky(float e) { return (e >= 0.f) ? e : NEG * e; }
__device__ __forceinline__ uint32_t pack_bf16x2(float a, float b) {
    __nv_bfloat162 p = __float22bfloat162_rn(make_float2(a, b));
    return *(uint32_t*)&p;
}
__device__ __forceinline__ uint32_t smem_u32(const void* p) {
    uint32_t a;
    asm("{ .reg .u64 t; cvta.to.shared.u64 t, %1; cvt.u32.u64 %0, t; }" : "=r"(a) : "l"(p));
    return a;
}
__device__ __forceinline__ uint32_t cluster_rank() {
    uint32_t r;
    asm("mov.u32 %0, %%cluster_ctarank;" : "=r"(r));
    return r;
}
__device__ __forceinline__ float dsmem_ld(uint32_t addr, uint32_t rank) {
    uint32_t ra; float v;
    asm("mapa.shared::cluster.u32 %0, %1, %2;" : "=r"(ra) : "r"(addr), "r"(rank));
    asm volatile("ld.shared::cluster.f32 %0, [%1];" : "=f"(v) : "r"(ra));
    return v;
}
#define CLUSTER_SYNC() do {                                            \
    asm volatile("barrier.cluster.arrive.aligned;" ::: "memory");      \
    asm volatile("barrier.cluster.wait.aligned;" ::: "memory");        \
} while (0)

// ---------------- prep: pos/emb zero + q vectors + knot sort + PWL table ----------------
__global__ void k_prep2(const float* __restrict__ W1, const float* __restrict__ as1,
                        const float* __restrict__ ad1, const float* __restrict__ b1,
                        const float* __restrict__ W2) {
    int h = blockIdx.x, tid = threadIdx.x;
    for (int i = h * 256 + tid; i < KSNAP * NNODE; i += 2048) g_pos[i] = 0;
    if (h == 0 && tid < 256) {
#pragma unroll
        for (int k = 0; k < KSNAP; k++) g_emb[k * D2 + tid] = 0.f;
    }

    __shared__ int perm_s[32];
    __shared__ float ws_s[32], bs_s[32];
    if (tid < 32) {
        int c = h * 32 + tid;
        float w = W1[c];
        float vs = warp_sum(w * as1[c]);
        float vd = warp_sum(w * ad1[c]);
        if (tid == 0) { g_q[h] = vs; g_q[8 + h] = vd; }
        float b = b1[c];
        float th = (w != 0.f) ? (-b / w) : 1e30f;
        unsigned rank = 0;
#pragma unroll
        for (int j = 0; j < 32; j++) {
            float tj = __shfl_sync(0xffffffffu, th, j);
            rank += (tj < th) || (tj == th && j < tid);
        }
        perm_s[rank] = tid;
        ws_s[rank] = w;
        bs_s[rank] = b;
        g_theta[h * 32 + rank] = th;
    }
    __syncthreads();

    int j = tid;
    float wv[32], bv[32], w2v[32];
#pragma unroll
    for (int r = 0; r < 32; r++) {
        int k = perm_s[r];
        w2v[r] = W2[(h * 32 + k) * 256 + j];
        wv[r]  = ws_s[r];
        bv[r]  = bs_s[r];
    }
    float slope = 0.f, intr = 0.f;
#pragma unroll
    for (int r = 0; r < 32; r++) {
        if (wv[r] < 0.f)                      { slope = fmaf(wv[r], w2v[r], slope); intr = fmaf(bv[r], w2v[r], intr); }
        else if (wv[r] == 0.f && bv[r] > 0.f) { intr = fmaf(bv[r], w2v[r], intr); }
    }
    g_tab[((h * 33 + 0) * 2 + 0) * 256 + j] = slope;
    g_tab[((h * 33 + 0) * 2 + 1) * 256 + j] = intr;
#pragma unroll
    for (int r = 1; r <= 32; r++) {
        float w = wv[r - 1], b = bv[r - 1], w2 = w2v[r - 1];
        if (w > 0.f)      { slope = fmaf(w, w2, slope);  intr = fmaf(b, w2, intr); }
        else if (w < 0.f) { slope = fmaf(-w, w2, slope); intr = fmaf(-b, w2, intr); }
        g_tab[((h * 33 + r) * 2 + 0) * 256 + j] = slope;
        g_tab[((h * 33 + r) * 2 + 1) * 256 + j] = intr;
    }
}

// ---------------- single-pass bucketed adjacency build ----------------
__global__ void k_scatter1(const int* __restrict__ ei) {
    int base = (blockIdx.x * blockDim.x + threadIdx.x) * 4;
    int src[4], node[4]; bool ok[4];
#pragma unroll
    for (int i = 0; i < 4; i++) {
        int idx = base + i;
        ok[i] = idx < ETOT;
        if (ok[i]) {
            int k = idx / EPTOT, e = idx - k * EPTOT;
            if (e < NEDGE) {
                src[i]  = ei[(k * 2 + 0) * NEDGE + e];
                node[i] = k * NNODE + ei[(k * 2 + 1) * NEDGE + e];
            } else {
                src[i]  = e - NEDGE;
                node[i] = k * NNODE + (e - NEDGE);
            }
        }
    }
#pragma unroll
    for (int i = 0; i < 4; i++) {
        if (ok[i]) {
            int slot = atomicAdd(&g_pos[node[i]], 1);
            if (slot < CAP)
                g_adjB[(long)node[i] * CAP + slot] = src[i];
        }
    }
}

// ---------------- layer-1 GAT + fused PWL feature construction ----------------
__global__ __launch_bounds__(256) void k_agg1(const float* __restrict__ xs,
                                              const float* __restrict__ as2,
                                              const float* __restrict__ ad2) {
    int k = blockIdx.y;
    int nn = blockIdx.x * 8 + (threadIdx.x >> 5);
    int lane = threadIdx.x & 31;
    int base = k * NNODE;
    int n = base + nn;
    int deg = min(g_pos[n], CAP);
    const int* adj = &g_adjB[(long)n * CAP];
    const float* xsk = xs + base;

    float qs[HEADS], dterm[HEADS];
    float xd = xsk[nn];
#pragma unroll
    for (int i = 0; i < HEADS; i++) { qs[i] = g_q[i]; dterm[i] = xd * g_q[8 + i]; }

    float m[HEADS], dsum[HEADS], tt[HEADS];

    if (deg <= 32) {
        float xv = 0.f;
        if (lane < deg) xv = xsk[adj[lane]];
        float xmx = warp_max((lane < deg) ? xv : -1e30f);
        float xmn = warp_min((lane < deg) ? xv :  1e30f);
#pragma unroll
        for (int i = 0; i < HEADS; i++)
            m[i] = lky(fmaf(qs[i], (qs[i] >= 0.f) ? xmx : xmn, dterm[i]));
#pragma unroll
        for (int i = 0; i < HEADS; i++) {
            float e = lky(fmaf(xv, qs[i], dterm[i]));
            float ex = (lane < deg) ? __expf(e - m[i]) : 0.f;
            dsum[i] = ex;
            tt[i] = ex * xv;
        }
    } else {
        float xmx = -1e30f, xmn = 1e30f;
        for (int j = lane; j < deg; j += 32) {
            float xv = xsk[adj[j]];
            xmx = fmaxf(xmx, xv); xmn = fminf(xmn, xv);
        }
        xmx = warp_max(xmx); xmn = warp_min(xmn);
#pragma unroll
        for (int i = 0; i < HEADS; i++)
            m[i] = lky(fmaf(qs[i], (qs[i] >= 0.f) ? xmx : xmn, dterm[i]));
#pragma unroll
        for (int i = 0; i < HEADS; i++) { dsum[i] = 0.f; tt[i] = 0.f; }
        for (int j = lane; j < deg; j += 32) {
            float xv = xsk[adj[j]];
#pragma unroll
            for (int i = 0; i < HEADS; i++) {
                float e = lky(fmaf(xv, qs[i], dterm[i]));
                float ex = __expf(e - m[i]);
                dsum[i] += ex;
                tt[i] = fmaf(ex, xv, tt[i]);
            }
        }
    }
    float tv[HEADS];
#pragma unroll
    for (int i = 0; i < HEADS; i++) {
        float ds = warp_sum(dsum[i]);
        float ts = warp_sum(tt[i]);
        tv[i] = ts / (ds + 1e-16f);
    }

    // fused PWL
    float y0 = (lane & 4) ? tv[4] : tv[0];
    float y1 = (lane & 4) ? tv[5] : tv[1];
    float y2 = (lane & 4) ? tv[6] : tv[2];
    float y3 = (lane & 4) ? tv[7] : tv[3];
    float z0 = (lane & 2) ? y2 : y0;
    float z1 = (lane & 2) ? y3 : y1;
    float tvh = (lane & 1) ? z1 : z0;
    int r = 0;
    if (lane < 8) {
        const float* th = &g_theta[lane * 32];
#pragma unroll
        for (int q = 0; q < 32; q++) r += (th[q] < tvh);
    }

    int j0 = lane * 8;
    float acc[8];
#pragma unroll
    for (int q = 0; q < 8; q++) acc[q] = 0.f;
#pragma unroll
    for (int h = 0; h < 8; h++) {
        float th = tv[h];
        int rh = __shfl_sync(0xffffffffu, r, h);
        const float* S = &g_tab[(long)((h * 33 + rh) * 2) * 256 + j0];
        float4 s0 = *(const float4*)S;
        float4 s1 = *(const float4*)(S + 4);
        float4 i0 = *(const float4*)(S + 256);
        float4 i1 = *(const float4*)(S + 260);
        acc[0] = fmaf(s0.x, th, acc[0] + i0.x);
        acc[1] = fmaf(s0.y, th, acc[1] + i0.y);
        acc[2] = fmaf(s0.z, th, acc[2] + i0.z);
        acc[3] = fmaf(s0.w, th, acc[3] + i0.w);
        acc[4] = fmaf(s1.x, th, acc[4] + i1.x);
        acc[5] = fmaf(s1.y, th, acc[5] + i1.y);
        acc[6] = fmaf(s1.z, th, acc[6] + i1.z);
        acc[7] = fmaf(s1.w, th, acc[7] + i1.w);
    }

    uint4 pkd = make_uint4(pack_bf16x2(acc[0], acc[1]), pack_bf16x2(acc[2], acc[3]),
                           pack_bf16x2(acc[4], acc[5]), pack_bf16x2(acc[6], acc[7]));
    *(uint4*)&g_featb[(long)n * 128 + lane * 4] = pkd;

    float ss = 0.f, sd = 0.f;
#pragma unroll
    for (int q = 0; q < 8; q++) {
        ss = fmaf(acc[q], as2[j0 + q], ss);
        sd = fmaf(acc[q], ad2[j0 + q], sd);
    }
    ss += __shfl_xor_sync(0xffffffffu, ss, 1);
    ss += __shfl_xor_sync(0xffffffffu, ss, 2);
    sd += __shfl_xor_sync(0xffffffffu, sd, 1);
    sd += __shfl_xor_sync(0xffffffffu, sd, 2);
    if ((lane & 3) == 0) {
        g_ssrc[(long)n * HEADS + (lane >> 2)] = ss;
        g_sdst[(long)n * HEADS + (lane >> 2)] = sd;
    }
}

// ---------------- layer-2 GAT aggregation: 2 warps per node + CTA-pooled mean ----------------
// R14 ncu: issue 54%, occ 48% -> parallelism-starved serial edge loop.
// Warp pair (2q, 2q+1) splits node q's edges (j = hf, hf+2, ...): halves the
// dependent chain and doubles resident warps per node. Partials combine in smem.
__global__ __launch_bounds__(256) void k_agg2(const float* __restrict__ bias) {
    __shared__ float s_m[8][8];      // per-warp partial max per head
    __shared__ float s_ds[8][8];     // per-warp partial dsum per head
    __shared__ float pool[8][256];   // per-warp partial feature accumulators
    int k = blockIdx.y;
    int w = threadIdx.x >> 5;        // warp 0..7
    int q = w >> 1;                  // node slot 0..3
    int hf = w & 1;                  // edge half
    int nn = blockIdx.x * 4 + q;
    int lane = threadIdx.x & 31;
    int base = k * NNODE;
    int n = base + nn;
    int deg = min(g_pos[n], CAP);
    const int* adj = &g_adjB[(long)n * CAP];
    const float* srcS = g_ssrc + (long)base * HEADS;
    const uint4* fb = (const uint4*)g_featb + (long)base * 32 + lane;

    // max pass: 64 lanes cover all <=64 edges in one gathered load
    float mx[HEADS];
#pragma unroll
    for (int i = 0; i < HEADS; i++) mx[i] = -1e30f;
    int je = hf * 32 + lane;
    if (je < deg) {
        const float4* sp = (const float4*)(srcS + adj[je] * 8);
        float4 s0 = sp[0], s1 = sp[1];
        mx[0] = s0.x; mx[1] = s0.y; mx[2] = s0.z; mx[3] = s0.w;
        mx[4] = s1.x; mx[5] = s1.y; mx[6] = s1.z; mx[7] = s1.w;
    }
#pragma unroll
    for (int i = 0; i < HEADS; i++) mx[i] = warp_max(mx[i]);
    if (lane == 0) {
#pragma unroll
        for (int i = 0; i < HEADS; i++) s_m[w][i] = mx[i];
    }
    __syncthreads();

    int hl = lane >> 2;
    float sd_l = g_sdst[(long)n * HEADS + hl];
    float m_l = lky(fmaxf(s_m[2 * q][hl], s_m[2 * q + 1][hl]) + sd_l);
    const float* srcH = srcS + hl;

    // gather pass over this warp's half of the edges
    float dsum = 0.f;
    unsigned long long a01 = 0ull, a23 = 0ull, a45 = 0ull, a67 = 0ull;
    for (int j = hf; j < deg; j += 2) {
        int s = adj[j];
        float e = srcH[s * 8];
        uint4 fv = fb[s * 32];
        float al = __expf(lky(e + sd_l) - m_l);
        dsum += al;
        unsigned long long al2 = dup2(al);
        FMA2(a01, bf2f2(fv.x), al2);
        FMA2(a23, bf2f2(fv.y), al2);
        FMA2(a45, bf2f2(fv.z), al2);
        FMA2(a67, bf2f2(fv.w), al2);
    }
    float a0, a1, a2, a3, a4, a5, a6, a7;
    unpack2(a01, a0, a1); unpack2(a23, a2, a3);
    unpack2(a45, a4, a5); unpack2(a67, a6, a7);

    if ((lane & 3) == 0) s_ds[w][hl] = dsum;
    float* pw = &pool[w][lane * 8];
    pw[0] = a0; pw[1] = a1; pw[2] = a2; pw[3] = a3;
    pw[4] = a4; pw[5] = a5; pw[6] = a6; pw[7] = a7;
    __syncthreads();

    // combine halves + normalize + bias + relu + pool over the 4 nodes
    int c = threadIdx.x;
    float bc = bias[c];
    int hd = c >> 5;
    float s8 = 0.f;
#pragma unroll
    for (int q2 = 0; q2 < 4; q2++) {
        float ds = s_ds[2 * q2][hd] + s_ds[2 * q2 + 1][hd];
        float inv = 1.f / (ds + 1e-16f);
        float v = fmaf(pool[2 * q2][c] + pool[2 * q2 + 1][c], inv, bc);
        s8 += fmaxf(v, 0.f);
    }
    atomicAdd(&g_emb[k * D2 + c], s8 * (1.0f / NNODE));
}

// ---------------- LSTM input projections ----------------
__global__ void k_xw(const float* __restrict__ Wih_f, const float* __restrict__ Wih_b) {
    int gid = blockIdx.x * 8 + (threadIdx.x >> 5);
    int lane = threadIdx.x & 31;
    int d = gid >> 13;
    int rem = gid & 8191;
    int k = rem >> 10;
    int g = rem & 1023;
    const float* Wih = d ? Wih_b : Wih_f;
    float s = 0.f;
    for (int j = lane; j < D2; j += 32)
        s += Wih[g * D2 + j] * g_emb[k * D2 + j];
    s = warp_sum(s);
    if (lane == 0) g_xw[gid] = s;
}

__global__ void k_whhT(const float* __restrict__ Whh_f, const float* __restrict__ Whh_b) {
    int idx = blockIdx.x * blockDim.x + threadIdx.x;
    if (idx >= 2 * 128 * 1024) return;
    int d = idx >> 17;
    int r = idx & ((1 << 17) - 1);
    int j2 = r >> 10;
    int t = r & 1023;
    const float* W = d ? Whh_b : Whh_f;
    g_whhT2[(((long)d * 128 + j2) << 10) + t] = make_float2(W[t * 256 + 2 * j2], W[t * 256 + 2 * j2 + 1]);
}

// ---------------- bidirectional LSTM: 4-CTA cluster per direction ----------------
__global__ __launch_bounds__(1024) __cluster_dims__(4, 1, 1)
void k_lstm(const float* __restrict__ bih_f, const float* __restrict__ bhh_f,
            const float* __restrict__ bih_b, const float* __restrict__ bhh_b,
            float* __restrict__ out) {
    int d = blockIdx.x >> 2;
    uint32_t rank = cluster_rank();
    int t = threadIdx.x;

    __shared__ __align__(16) float ps[2][1024];
    __shared__ __align__(16) float hloc[64];
    __shared__ float g4[256];
    __shared__ float xw_s[KSNAP][256];

    const float* bih = d ? bih_b : bih_f;
    const float* bhh = d ? bhh_b : bhh_f;

    int gidx = (t >> 6) * 256 + rank * 64 + (t & 63);
    if (t < 256) {
        float bsum = bih[gidx] + bhh[gidx];
#pragma unroll
        for (int k = 0; k < KSNAP; k++) {
            int kk = d ? (KSNAP - 1 - k) : k;
            xw_s[k][t] = g_xw[((long)d * KSNAP + kk) * 1024 + gidx] + bsum;
        }
    }
    if (t < 64) hloc[t] = 0.f;
    float cstate = 0.f;

    const unsigned long long* WT =
        (const unsigned long long*)(g_whhT2 + (long)d * 128 * 1024) + (long)(rank * 32) * 1024 + t;
    const unsigned long long* hp = (const unsigned long long*)hloc;
    uint32_t ps_base = smem_u32(&ps[0][0]);

    __syncthreads();
    CLUSTER_SYNC();

    int b = 0;
    for (int step = 0; step < KSNAP; step++) {
        unsigned long long acc2 = 0ull;
#pragma unroll
        for (int jj = 0; jj < 32; jj++)
            FMA2(acc2, WT[(long)jj * 1024], hp[jj]);
        float lo, hi;
        unpack2(acc2, lo, hi);
        ps[b][t] = lo + hi;
        __syncthreads();
        CLUSTER_SYNC();

        if (t < 256) {
            uint32_t pa = ps_base + (b * 1024 + gidx) * 4;
            float v = xw_s[step][t];
            v += dsmem_ld(pa, 0);
            v += dsmem_ld(pa, 1);
            v += dsmem_ld(pa, 2);
            v += dsmem_ld(pa, 3);
            g4[t] = v;
        }
        __syncthreads();

        if (t < 64) {
            float ig = 1.f / (1.f + expf(-g4[t]));
            float fg = 1.f / (1.f + expf(-g4[64 + t]));
            float gg = tanhf(g4[128 + t]);
            float og = 1.f / (1.f + expf(-g4[192 + t]));
            cstate = fg * cstate + ig * gg;
            hloc[t] = og * tanhf(cstate);
        }
        __syncthreads();
        b ^= 1;
    }

    if (t < 64) out[d * LH + rank * 64 + t] = hloc[t];
    CLUSTER_SYNC();
}

// ---------------- launch ----------------
extern "C" void kernel_launch(void* const* d_in, const int* in_sizes, int n_in,
                              void* d_out, int out_size) {
    const float* xs     = (const float*)d_in[0];
    const int*   ei     = (const int*)  d_in[1];
    const float* W1     = (const float*)d_in[2];
    const float* a_src1 = (const float*)d_in[3];
    const float* a_dst1 = (const float*)d_in[4];
    const float* b1     = (const float*)d_in[5];
    const float* W2     = (const float*)d_in[6];
    const float* a_src2 = (const float*)d_in[7];
    const float* a_dst2 = (const float*)d_in[8];
    const float* b2     = (const float*)d_in[9];
    const float* Wih_f  = (const float*)d_in[10];
    const float* Whh_f  = (const float*)d_in[11];
    const float* bih_f  = (const float*)d_in[12];
    const float* bhh_f  = (const float*)d_in[13];
    const float* Wih_b  = (const float*)d_in[14];
    const float* Whh_b  = (const float*)d_in[15];
    const float* bih_b  = (const float*)d_in[16];
    const float* bhh_b  = (const float*)d_in[17];
    float* out = (float*)d_out;

    k_prep2<<<HEADS, 256>>>(W1, a_src1, a_dst1, b1, W2);
    k_scatter1<<<(ETOT / 4 + 255) / 256, 256>>>(ei);

    k_agg1<<<dim3(NNODE / 8, KSNAP), 256>>>(xs, a_src2, a_dst2);
    k_agg2<<<dim3(NNODE / 4, KSNAP), 256>>>(b2);

    k_whhT<<<(2 * 128 * 1024 + 255) / 256, 256>>>(Whh_f, Whh_b);
    k_xw<<<2048, 256>>>(Wih_f, Wih_b);
    k_lstm<<<8, 1024>>>(bih_f, bhh_f, bih_b, bhh_b, out);
}

// round 16
// speedup vs baseline: 1.1971x; 1.1971x over previous
#include <cuda_runtime.h>
#include <cuda_bf16.h>
#include <cstdint>

// ---------------- problem constants ----------------
#define KSNAP 8
#define NNODE 10000
#define NEDGE 160000
#define EPTOT (NEDGE + NNODE)   // edges + self loops = 170000
#define HEADS 8
#define D2 256
#define LH 256
#define NEG 0.2f
#define NTOT (KSNAP * NNODE)    // 80000
#define ETOT (KSNAP * EPTOT)    // 1360000
#define CAP 64                  // adjacency bucket capacity

// ---------------- static scratch ----------------
static __device__ unsigned int g_featb[NTOT * 128];    // h_lin bf16x2 packed
static __device__ float g_ssrc[NTOT * HEADS];
static __device__ float g_sdst[NTOT * HEADS];
static __device__ float g_q   [2 * HEADS];
static __device__ float g_theta[HEADS * 32];
static __device__ float g_tab  [HEADS * 33 * 2 * 256];
static __device__ int   g_pos [KSNAP * NNODE];
static __device__ int   g_adjB[NTOT * CAP];
static __device__ float g_emb [KSNAP * D2];
static __device__ float g_xw  [2 * KSNAP * 4 * LH];
static __device__ float2 g_whhT2[2 * 128 * 1024];

// ---------------- helpers ----------------
__device__ __forceinline__ float warp_sum(float v) {
#pragma unroll
    for (int o = 16; o; o >>= 1) v += __shfl_xor_sync(0xffffffffu, v, o);
    return v;
}
#define FMA2(d, a, b) asm("fma.rn.f32x2 %0, %1, %2, %0;" : "+l"(d) : "l"(a), "l"(b))
__device__ __forceinline__ void unpack2(unsigned long long v, float& lo, float& hi) {
    lo = __uint_as_float((unsigned int)(v & 0xffffffffull));
    hi = __uint_as_float((unsigned int)(v >> 32));
}
__device__ __forceinline__ float lky(float e) { return (e >= 0.f) ? e : NEG * e; }
__device__ __forceinline__ uint32_t pack_bf16x2(float a, float b) {
    __nv_bfloat162 p = __float22bfloat162_rn(make_float2(a, b));
    return *(uint32_t*)&p;
}
__device__ __forceinline__ uint32_t smem_u32(const void* p) {
    uint32_t a;
    asm("{ .reg .u64 t; cvta.to.shared.u64 t, %1; cvt.u32.u64 %0, t; }" : "=r"(a) : "l"(p));
    return a;
}
__device__ __forceinline__ uint32_t cluster_rank() {
    uint32_t r;
    asm("mov.u32 %0, %%cluster_ctarank;" : "=r"(r));
    return r;
}
__device__ __forceinline__ float dsmem_ld(uint32_t addr, uint32_t rank) {
    uint32_t ra; float v;
    asm("mapa.shared::cluster.u32 %0, %1, %2;" : "=r"(ra) : "r"(addr), "r"(rank));
    asm volatile("ld.shared::cluster.f32 %0, [%1];" : "=f"(v) : "r"(ra));
    return v;
}
#define CLUSTER_SYNC() do {                                            \
    asm volatile("barrier.cluster.arrive.aligned;" ::: "memory");      \
    asm volatile("barrier.cluster.wait.aligned;" ::: "memory");        \
} while (0)

// ---------------- prep: pos/emb zero + q vectors + knot sort + PWL table ----------------
__global__ void k_prep2(const float* __restrict__ W1, const float* __restrict__ as1,
                        const float* __restrict__ ad1, const float* __restrict__ b1,
                        const float* __restrict__ W2) {
    int h = blockIdx.x, tid = threadIdx.x;
    for (int i = h * 256 + tid; i < KSNAP * NNODE; i += 2048) g_pos[i] = 0;
    if (h == 0 && tid < 256) {
#pragma unroll
        for (int k = 0; k < KSNAP; k++) g_emb[k * D2 + tid] = 0.f;
    }

    __shared__ int perm_s[32];
    __shared__ float ws_s[32], bs_s[32];
    if (tid < 32) {
        int c = h * 32 + tid;
        float w = W1[c];
        float vs = warp_sum(w * as1[c]);
        float vd = warp_sum(w * ad1[c]);
        if (tid == 0) { g_q[h] = vs; g_q[8 + h] = vd; }
        float b = b1[c];
        float th = (w != 0.f) ? (-b / w) : 1e30f;
        unsigned rank = 0;
#pragma unroll
        for (int j = 0; j < 32; j++) {
            float tj = __shfl_sync(0xffffffffu, th, j);
            rank += (tj < th) || (tj == th && j < tid);
        }
        perm_s[rank] = tid;
        ws_s[rank] = w;
        bs_s[rank] = b;
        g_theta[h * 32 + rank] = th;
    }
    __syncthreads();

    int j = tid;
    float wv[32], bv[32], w2v[32];
#pragma unroll
    for (int r = 0; r < 32; r++) {
        int k = perm_s[r];
        w2v[r] = W2[(h * 32 + k) * 256 + j];
        wv[r]  = ws_s[r];
        bv[r]  = bs_s[r];
    }
    float slope = 0.f, intr = 0.f;
#pragma unroll
    for (int r = 0; r < 32; r++) {
        if (wv[r] < 0.f)                      { slope = fmaf(wv[r], w2v[r], slope); intr = fmaf(bv[r], w2v[r], intr); }
        else if (wv[r] == 0.f && bv[r] > 0.f) { intr = fmaf(bv[r], w2v[r], intr); }
    }
    g_tab[((h * 33 + 0) * 2 + 0) * 256 + j] = slope;
    g_tab[((h * 33 + 0) * 2 + 1) * 256 + j] = intr;
#pragma unroll
    for (int r = 1; r <= 32; r++) {
        float w = wv[r - 1], b = bv[r - 1], w2 = w2v[r - 1];
        if (w > 0.f)      { slope = fmaf(w, w2, slope);  intr = fmaf(b, w2, intr); }
        else if (w < 0.f) { slope = fmaf(-w, w2, slope); intr = fmaf(-b, w2, intr); }
        g_tab[((h * 33 + r) * 2 + 0) * 256 + j] = slope;
        g_tab[((h * 33 + r) * 2 + 1) * 256 + j] = intr;
    }
}

// ---------------- single-pass bucketed adjacency build ----------------
__global__ void k_scatter1(const int* __restrict__ ei) {
    int base = (blockIdx.x * blockDim.x + threadIdx.x) * 4;
    int src[4], node[4]; bool ok[4];
#pragma unroll
    for (int i = 0; i < 4; i++) {
        int idx = base + i;
        ok[i] = idx < ETOT;
        if (ok[i]) {
            int k = idx / EPTOT, e = idx - k * EPTOT;
            if (e < NEDGE) {
                src[i]  = ei[(k * 2 + 0) * NEDGE + e];
                node[i] = k * NNODE + ei[(k * 2 + 1) * NEDGE + e];
            } else {
                src[i]  = e - NEDGE;
                node[i] = k * NNODE + (e - NEDGE);
            }
        }
    }
#pragma unroll
    for (int i = 0; i < 4; i++) {
        if (ok[i]) {
            int slot = atomicAdd(&g_pos[node[i]], 1);
            if (slot < CAP)
                g_adjB[(long)node[i] * CAP + slot] = src[i];
        }
    }
}

// ---------------- layer-1 GAT (no-max softmax) + fused PWL ----------------
// e-values are tightly bounded (|e| ~ 1 << 88): exp(e)/sum(exp(e)) is the exact
// same alpha as the max-subtracted form up to fp32 rounding -> drop the max pass.
__global__ __launch_bounds__(256) void k_agg1(const float* __restrict__ xs,
                                              const float* __restrict__ as2,
                                              const float* __restrict__ ad2) {
    int k = blockIdx.y;
    int nn = blockIdx.x * 8 + (threadIdx.x >> 5);
    int lane = threadIdx.x & 31;
    int base = k * NNODE;
    int n = base + nn;
    int deg = min(g_pos[n], CAP);
    const int* adj = &g_adjB[(long)n * CAP];
    const float* xsk = xs + base;

    float qs[HEADS], dterm[HEADS];
    float xd = xsk[nn];
#pragma unroll
    for (int i = 0; i < HEADS; i++) { qs[i] = g_q[i]; dterm[i] = xd * g_q[8 + i]; }

    float dsum[HEADS], tt[HEADS];

    if (deg <= 32) {
        float xv = 0.f;
        if (lane < deg) xv = xsk[adj[lane]];
#pragma unroll
        for (int i = 0; i < HEADS; i++) {
            float e = lky(fmaf(xv, qs[i], dterm[i]));
            float ex = (lane < deg) ? __expf(e) : 0.f;
            dsum[i] = ex;
            tt[i] = ex * xv;
        }
    } else {
#pragma unroll
        for (int i = 0; i < HEADS; i++) { dsum[i] = 0.f; tt[i] = 0.f; }
        for (int j = lane; j < deg; j += 32) {
            float xv = xsk[adj[j]];
#pragma unroll
            for (int i = 0; i < HEADS; i++) {
                float e = lky(fmaf(xv, qs[i], dterm[i]));
                float ex = __expf(e);
                dsum[i] += ex;
                tt[i] = fmaf(ex, xv, tt[i]);
            }
        }
    }
    float tv[HEADS];
#pragma unroll
    for (int i = 0; i < HEADS; i++) {
        float ds = warp_sum(dsum[i]);
        float ts = warp_sum(tt[i]);
        tv[i] = ts / (ds + 1e-16f);
    }

    // fused PWL
    float y0 = (lane & 4) ? tv[4] : tv[0];
    float y1 = (lane & 4) ? tv[5] : tv[1];
    float y2 = (lane & 4) ? tv[6] : tv[2];
    float y3 = (lane & 4) ? tv[7] : tv[3];
    float z0 = (lane & 2) ? y2 : y0;
    float z1 = (lane & 2) ? y3 : y1;
    float tvh = (lane & 1) ? z1 : z0;
    int r = 0;
    if (lane < 8) {
        const float* th = &g_theta[lane * 32];
#pragma unroll
        for (int q = 0; q < 32; q++) r += (th[q] < tvh);
    }

    int j0 = lane * 8;
    float acc[8];
#pragma unroll
    for (int q = 0; q < 8; q++) acc[q] = 0.f;
#pragma unroll
    for (int h = 0; h < 8; h++) {
        float th = tv[h];
        int rh = __shfl_sync(0xffffffffu, r, h);
        const float* S = &g_tab[(long)((h * 33 + rh) * 2) * 256 + j0];
        float4 s0 = *(const float4*)S;
        float4 s1 = *(const float4*)(S + 4);
        float4 i0 = *(const float4*)(S + 256);
        float4 i1 = *(const float4*)(S + 260);
        acc[0] = fmaf(s0.x, th, acc[0] + i0.x);
        acc[1] = fmaf(s0.y, th, acc[1] + i0.y);
        acc[2] = fmaf(s0.z, th, acc[2] + i0.z);
        acc[3] = fmaf(s0.w, th, acc[3] + i0.w);
        acc[4] = fmaf(s1.x, th, acc[4] + i1.x);
        acc[5] = fmaf(s1.y, th, acc[5] + i1.y);
        acc[6] = fmaf(s1.z, th, acc[6] + i1.z);
        acc[7] = fmaf(s1.w, th, acc[7] + i1.w);
    }

    uint4 pkd = make_uint4(pack_bf16x2(acc[0], acc[1]), pack_bf16x2(acc[2], acc[3]),
                           pack_bf16x2(acc[4], acc[5]), pack_bf16x2(acc[6], acc[7]));
    *(uint4*)&g_featb[(long)n * 128 + lane * 4] = pkd;

    float ss = 0.f, sd = 0.f;
#pragma unroll
    for (int q = 0; q < 8; q++) {
        ss = fmaf(acc[q], as2[j0 + q], ss);
        sd = fmaf(acc[q], ad2[j0 + q], sd);
    }
    ss += __shfl_xor_sync(0xffffffffu, ss, 1);
    ss += __shfl_xor_sync(0xffffffffu, ss, 2);
    sd += __shfl_xor_sync(0xffffffffu, sd, 1);
    sd += __shfl_xor_sync(0xffffffffu, sd, 2);
    if ((lane & 3) == 0) {
        g_ssrc[(long)n * HEADS + (lane >> 2)] = ss;
        g_sdst[(long)n * HEADS + (lane >> 2)] = sd;
    }
}

// ---------------- layer-2 GAT aggregation (no-max softmax) + CTA-pooled mean ----------------
// One warp per node (R13's best-measured config), no max pass: single gather loop.
__global__ __launch_bounds__(256) void k_agg2(const float* __restrict__ bias) {
    __shared__ float pool[8][256];
    int k = blockIdx.y;
    int w = threadIdx.x >> 5;
    int nn = blockIdx.x * 8 + w;
    int lane = threadIdx.x & 31;
    int base = k * NNODE;
    int n = base + nn;
    int deg = min(g_pos[n], CAP);
    const int* adj = &g_adjB[(long)n * CAP];
    int hl = lane >> 2;
    const float* srcH = g_ssrc + (long)base * HEADS + hl;
    const uint4* fb = (const uint4*)g_featb + (long)base * 32 + lane;
    float sd_l = g_sdst[(long)n * HEADS + hl];

    float dsum = 0.f;
    float a0 = 0.f, a1 = 0.f, a2 = 0.f, a3 = 0.f, a4 = 0.f, a5 = 0.f, a6 = 0.f, a7 = 0.f;
    int j = 0;
    for (; j + 2 <= deg; j += 2) {
        int sA = adj[j], sB = adj[j + 1];
        float eA = srcH[sA * 8];
        float eB = srcH[sB * 8];
        uint4 fvA = fb[sA * 32];
        uint4 fvB = fb[sB * 32];
        float alA = __expf(lky(eA + sd_l));
        float alB = __expf(lky(eB + sd_l));
        dsum += alA + alB;
        {
            float2 f0 = __bfloat1622float2(*(__nv_bfloat162*)&fvA.x);
            float2 f1 = __bfloat1622float2(*(__nv_bfloat162*)&fvA.y);
            float2 f2 = __bfloat1622float2(*(__nv_bfloat162*)&fvA.z);
            float2 f3 = __bfloat1622float2(*(__nv_bfloat162*)&fvA.w);
            a0 = fmaf(f0.x, alA, a0); a1 = fmaf(f0.y, alA, a1);
            a2 = fmaf(f1.x, alA, a2); a3 = fmaf(f1.y, alA, a3);
            a4 = fmaf(f2.x, alA, a4); a5 = fmaf(f2.y, alA, a5);
            a6 = fmaf(f3.x, alA, a6); a7 = fmaf(f3.y, alA, a7);
        }
        {
            float2 f0 = __bfloat1622float2(*(__nv_bfloat162*)&fvB.x);
            float2 f1 = __bfloat1622float2(*(__nv_bfloat162*)&fvB.y);
            float2 f2 = __bfloat1622float2(*(__nv_bfloat162*)&fvB.z);
            float2 f3 = __bfloat1622float2(*(__nv_bfloat162*)&fvB.w);
            a0 = fmaf(f0.x, alB, a0); a1 = fmaf(f0.y, alB, a1);
            a2 = fmaf(f1.x, alB, a2); a3 = fmaf(f1.y, alB, a3);
            a4 = fmaf(f2.x, alB, a4); a5 = fmaf(f2.y, alB, a5);
            a6 = fmaf(f3.x, alB, a6); a7 = fmaf(f3.y, alB, a7);
        }
    }
    for (; j < deg; j++) {
        int s = adj[j];
        float e = srcH[s * 8];
        uint4 fv = fb[s * 32];
        float al = __expf(lky(e + sd_l));
        dsum += al;
        float2 f0 = __bfloat1622float2(*(__nv_bfloat162*)&fv.x);
        float2 f1 = __bfloat1622float2(*(__nv_bfloat162*)&fv.y);
        float2 f2 = __bfloat1622float2(*(__nv_bfloat162*)&fv.z);
        float2 f3 = __bfloat1622float2(*(__nv_bfloat162*)&fv.w);
        a0 = fmaf(f0.x, al, a0); a1 = fmaf(f0.y, al, a1);
        a2 = fmaf(f1.x, al, a2); a3 = fmaf(f1.y, al, a3);
        a4 = fmaf(f2.x, al, a4); a5 = fmaf(f2.y, al, a5);
        a6 = fmaf(f3.x, al, a6); a7 = fmaf(f3.y, al, a7);
    }
    float inv = 1.f / (dsum + 1e-16f);
    float4 b0 = *(const float4*)&bias[lane * 8];
    float4 b1v = *(const float4*)&bias[lane * 8 + 4];
    float* pw = &pool[w][lane * 8];
    pw[0] = fmaxf(fmaf(a0, inv, b0.x), 0.f);
    pw[1] = fmaxf(fmaf(a1, inv, b0.y), 0.f);
    pw[2] = fmaxf(fmaf(a2, inv, b0.z), 0.f);
    pw[3] = fmaxf(fmaf(a3, inv, b0.w), 0.f);
    pw[4] = fmaxf(fmaf(a4, inv, b1v.x), 0.f);
    pw[5] = fmaxf(fmaf(a5, inv, b1v.y), 0.f);
    pw[6] = fmaxf(fmaf(a6, inv, b1v.z), 0.f);
    pw[7] = fmaxf(fmaf(a7, inv, b1v.w), 0.f);
    __syncthreads();

    int c = threadIdx.x;
    float s8 = pool[0][c] + pool[1][c] + pool[2][c] + pool[3][c]
             + pool[4][c] + pool[5][c] + pool[6][c] + pool[7][c];
    atomicAdd(&g_emb[k * D2 + c], s8 * (1.0f / NNODE));
}

// ---------------- LSTM input projections ----------------
__global__ void k_xw(const float* __restrict__ Wih_f, const float* __restrict__ Wih_b) {
    int gid = blockIdx.x * 8 + (threadIdx.x >> 5);
    int lane = threadIdx.x & 31;
    int d = gid >> 13;
    int rem = gid & 8191;
    int k = rem >> 10;
    int g = rem & 1023;
    const float* Wih = d ? Wih_b : Wih_f;
    float s = 0.f;
    for (int j = lane; j < D2; j += 32)
        s += Wih[g * D2 + j] * g_emb[k * D2 + j];
    s = warp_sum(s);
    if (lane == 0) g_xw[gid] = s;
}

__global__ void k_whhT(const float* __restrict__ Whh_f, const float* __restrict__ Whh_b) {
    int idx = blockIdx.x * blockDim.x + threadIdx.x;
    if (idx >= 2 * 128 * 1024) return;
    int d = idx >> 17;
    int r = idx & ((1 << 17) - 1);
    int j2 = r >> 10;
    int t = r & 1023;
    const float* W = d ? Whh_b : Whh_f;
    g_whhT2[(((long)d * 128 + j2) << 10) + t] = make_float2(W[t * 256 + 2 * j2], W[t * 256 + 2 * j2 + 1]);
}

// ---------------- bidirectional LSTM: 4-CTA cluster per direction ----------------
__global__ __launch_bounds__(1024) __cluster_dims__(4, 1, 1)
void k_lstm(const float* __restrict__ bih_f, const float* __restrict__ bhh_f,
            const float* __restrict__ bih_b, const float* __restrict__ bhh_b,
            float* __restrict__ out) {
    int d = blockIdx.x >> 2;
    uint32_t rank = cluster_rank();
    int t = threadIdx.x;

    __shared__ __align__(16) float ps[2][1024];
    __shared__ __align__(16) float hloc[64];
    __shared__ float g4[256];
    __shared__ float xw_s[KSNAP][256];

    const float* bih = d ? bih_b : bih_f;
    const float* bhh = d ? bhh_b : bhh_f;

    int gidx = (t >> 6) * 256 + rank * 64 + (t & 63);
    if (t < 256) {
        float bsum = bih[gidx] + bhh[gidx];
#pragma unroll
        for (int k = 0; k < KSNAP; k++) {
            int kk = d ? (KSNAP - 1 - k) : k;
            xw_s[k][t] = g_xw[((long)d * KSNAP + kk) * 1024 + gidx] + bsum;
        }
    }
    if (t < 64) hloc[t] = 0.f;
    float cstate = 0.f;

    const unsigned long long* WT =
        (const unsigned long long*)(g_whhT2 + (long)d * 128 * 1024) + (long)(rank * 32) * 1024 + t;
    const unsigned long long* hp = (const unsigned long long*)hloc;
    uint32_t ps_base = smem_u32(&ps[0][0]);

    __syncthreads();
    CLUSTER_SYNC();

    int b = 0;
    for (int step = 0; step < KSNAP; step++) {
        unsigned long long acc2 = 0ull;
#pragma unroll
        for (int jj = 0; jj < 32; jj++)
            FMA2(acc2, WT[(long)jj * 1024], hp[jj]);
        float lo, hi;
        unpack2(acc2, lo, hi);
        ps[b][t] = lo + hi;
        __syncthreads();
        CLUSTER_SYNC();

        if (t < 256) {
            uint32_t pa = ps_base + (b * 1024 + gidx) * 4;
            float v = xw_s[step][t];
            v += dsmem_ld(pa, 0);
            v += dsmem_ld(pa, 1);
            v += dsmem_ld(pa, 2);
            v += dsmem_ld(pa, 3);
            g4[t] = v;
        }
        __syncthreads();

        if (t < 64) {
            float ig = 1.f / (1.f + expf(-g4[t]));
            float fg = 1.f / (1.f + expf(-g4[64 + t]));
            float gg = tanhf(g4[128 + t]);
            float og = 1.f / (1.f + expf(-g4[192 + t]));
            cstate = fg * cstate + ig * gg;
            hloc[t] = og * tanhf(cstate);
        }
        __syncthreads();
        b ^= 1;
    }

    if (t < 64) out[d * LH + rank * 64 + t] = hloc[t];
    CLUSTER_SYNC();
}

// ---------------- launch ----------------
extern "C" void kernel_launch(void* const* d_in, const int* in_sizes, int n_in,
                              void* d_out, int out_size) {
    const float* xs     = (const float*)d_in[0];
    const int*   ei     = (const int*)  d_in[1];
    const float* W1     = (const float*)d_in[2];
    const float* a_src1 = (const float*)d_in[3];
    const float* a_dst1 = (const float*)d_in[4];
    const float* b1     = (const float*)d_in[5];
    const float* W2     = (const float*)d_in[6];
    const float* a_src2 = (const float*)d_in[7];
    const float* a_dst2 = (const float*)d_in[8];
    const float* b2     = (const float*)d_in[9];
    const float* Wih_f  = (const float*)d_in[10];
    const float* Whh_f  = (const float*)d_in[11];
    const float* bih_f  = (const float*)d_in[12];
    const float* bhh_f  = (const float*)d_in[13];
    const float* Wih_b  = (const float*)d_in[14];
    const float* Whh_b  = (const float*)d_in[15];
    const float* bih_b  = (const float*)d_in[16];
    const float* bhh_b  = (const float*)d_in[17];
    float* out = (float*)d_out;

    k_prep2<<<HEADS, 256>>>(W1, a_src1, a_dst1, b1, W2);
    k_scatter1<<<(ETOT / 4 + 255) / 256, 256>>>(ei);

    k_agg1<<<dim3(NNODE / 8, KSNAP), 256>>>(xs, a_src2, a_dst2);
    k_agg2<<<dim3(NNODE / 8, KSNAP), 256>>>(b2);

    k_whhT<<<(2 * 128 * 1024 + 255) / 256, 256>>>(Whh_f, Whh_b);
    k_xw<<<2048, 256>>>(Wih_f, Wih_b);
    k_lstm<<<8, 1024>>>(bih_f, bhh_f, bih_b, bhh_b, out);
}